// round 8
// baseline (speedup 1.0000x reference)
#include <cuda_runtime.h>
#include <math.h>

#define NCH 16
#define NB 5
#define MAXN 20000
#define MAXE 640000

// Scratch (allocation-free: __device__ globals; zero-initialized at module load)
__device__ int g_counts[MAXN];
__device__ int g_row[MAXN + 1];
__device__ int g_rank[MAXE];
__device__ float4 g_rec[MAXE];    // sorted: {ex, ey, ez, sender_bits}

// Histogram + per-edge rank in one pass. Requires g_counts == 0 on entry
// (true at load; k_scan re-zeroes after reading each call).
__global__ void k_hist(const int* __restrict__ recv, int E) {
    int i = blockIdx.x * blockDim.x + threadIdx.x;
    if (i < E) g_rank[i] = atomicAdd(&g_counts[recv[i]], 1);
}

// Single-block scan: thread-serial ITEMS + shfl warp scan + warp-totals scan.
// Also re-zeroes g_counts for the next kernel_launch call.
__global__ void k_scan(int n) {
    const int T = 1024;
    const int ITEMS = 20;
    int tid = threadIdx.x;
    int lane = tid & 31, wid = tid >> 5;
    int start = tid * ITEMS;

    int loc[ITEMS];
    int sum = 0;
    #pragma unroll
    for (int k = 0; k < ITEMS; k++) {
        int i = start + k;
        int v = (i < n) ? g_counts[i] : 0;
        loc[k] = sum;
        sum += v;
    }
    int s = sum;
    #pragma unroll
    for (int off = 1; off < 32; off <<= 1) {
        int t = __shfl_up_sync(0xffffffffu, s, off);
        if (lane >= off) s += t;
    }
    __shared__ int wsum[32];
    if (lane == 31) wsum[wid] = s;
    __syncthreads();
    if (wid == 0) {
        int w = wsum[lane];
        #pragma unroll
        for (int off = 1; off < 32; off <<= 1) {
            int t = __shfl_up_sync(0xffffffffu, w, off);
            if (lane >= off) w += t;
        }
        wsum[lane] = w;
    }
    __syncthreads();
    int base = (wid > 0 ? wsum[wid - 1] : 0) + (s - sum);
    #pragma unroll
    for (int k = 0; k < ITEMS; k++) {
        int i = start + k;
        if (i < n) { g_row[i] = base + loc[k]; g_counts[i] = 0; }
    }
    if (tid == T - 1) g_row[n] = wsum[31];
}

// Atomic-free scatter: ONE scattered 16-byte store per edge.
__global__ void k_scatter(const int* __restrict__ recv,
                          const int* __restrict__ senders,
                          const float* __restrict__ edges, int E) {
    int i = blockIdx.x * blockDim.x + threadIdx.x;
    if (i >= E) return;
    int pos = g_row[recv[i]] + g_rank[i];
    float ex = edges[3 * i + 0];
    float ey = edges[3 * i + 1];
    float ez = edges[3 * i + 2];
    g_rec[pos] = make_float4(ex, ey, ez, __int_as_float(senders[i]));
}

// Main gather: TWO warps per node (sub = wid&1), 4 nodes per 256-thread block.
// lane = (half<<4)|channel. Each warp-iteration: 4 edges, all loads hoisted.
// Halves combined via shfl, warp pairs combined via shared memory.
__global__ void __launch_bounds__(256, 4) k_main(
    const float* __restrict__ nodes0, const float* __restrict__ nodes1,
    const float* __restrict__ c00, const float* __restrict__ c01,
    const float* __restrict__ c10, const float* __restrict__ c11,
    const float* __restrict__ w000, const float* __restrict__ w011,
    const float* __restrict__ w101, const float* __restrict__ w110,
    const float* __restrict__ w111,
    float* __restrict__ out0, float* __restrict__ out1, int n_nodes)
{
    int wid = threadIdx.x >> 5;          // 0..7
    int node = blockIdx.x * 4 + (wid >> 1);
    int sub = wid & 1;
    int lane = threadIdx.x & 31;
    int c = lane & 15;
    int half = lane >> 4;
    bool active = (node < n_nodes);

    __shared__ float red[8][176];        // [warp][c*11 + k], stride 11: conflict-free

    // Radial coefficients with RBF constants K_k = exp(-0.7 c_k^2) pre-folded.
    const float Kf[NB] = {
        1.0f,
        (float)exp(-0.7 * 0.875 * 0.875),
        (float)exp(-0.7 * 1.75  * 1.75),
        (float)exp(-0.7 * 2.625 * 2.625),
        (float)exp(-0.7 * 3.5   * 3.5)
    };
    float a00[NB], a01[NB], a10[NB], a11[NB];
    #pragma unroll
    for (int k = 0; k < NB; k++) {
        a00[k] = c00[c * NB + k] * Kf[k];
        a01[k] = c01[c * NB + k] * Kf[k];
        a10[k] = c10[c * NB + k] * Kf[k];
        a11[k] = c11[c * NB + k] * Kf[k];
    }
    const float Y00 = 0.28209479177387814f;
    const float Y1C = 0.4886025119029199f;
    float W000f = w000[c] * Y00;
    float W011f = w011[c] * Y1C;
    float W101f = w101[c] * Y00;
    float W110f = w110[c] * 0.57735026918962576f * Y1C;  // 1/sqrt(3) * Y1C
    float W111f = w111[c] * 0.70710678118654752f * Y1C;  // 1/sqrt(2) * Y1C

    float m0a = 0.f, m0b = 0.f;
    float m1a0 = 0.f, m1a1 = 0.f, m1a2 = 0.f;
    float m1b0 = 0.f, m1b1 = 0.f, m1b2 = 0.f;
    float m1c0 = 0.f, m1c1 = 0.f, m1c2 = 0.f;

    if (active) {
        int rs = g_row[node];
        int re = g_row[node + 1];

        #pragma unroll 1
        for (int base = rs + sub * 4; base < re; base += 8) {
            int i0 = base + half;
            int i1 = base + 2 + half;
            bool v0 = (i0 < re);
            bool v1 = (i1 < re);
            // All memory in flight before compute: 2 recs + node feats for both.
            float4 rec0 = g_rec[v0 ? i0 : rs];
            float4 rec1 = g_rec[v1 ? i1 : rs];
            int s0 = __float_as_int(rec0.w);
            int s1 = __float_as_int(rec1.w);
            float n0v0 = nodes0[s0 * NCH + c];
            float n0v1 = nodes0[s1 * NCH + c];
            const float* p0 = nodes1 + ((size_t)s0 * NCH + c) * 3;
            const float* p1 = nodes1 + ((size_t)s1 * NCH + c) * 3;
            float n1x0 = p0[0], n1y0 = p0[1], n1z0 = p0[2];
            float n1x1 = p1[0], n1y1 = p1[1], n1z1 = p1[2];

            // ---- edge 0 geometry + radials ----
            {
                float ex = rec0.x, ey = rec0.y, ez = rec0.z;
                float r2 = fmaf(ex, ex, fmaf(ey, ey, ez * ez));
                float r  = sqrtf(r2);
                float E0 = __expf(-0.7f * r2);
                float t  = __expf(1.225f * r);
                float q1 = E0 * t, q2 = q1 * t, q3 = q2 * t, q4 = q3 * t;
                float rad00 = fmaf(q4, a00[4], fmaf(q3, a00[3], fmaf(q2, a00[2], fmaf(q1, a00[1], E0 * a00[0]))));
                float rad01 = fmaf(q4, a01[4], fmaf(q3, a01[3], fmaf(q2, a01[2], fmaf(q1, a01[1], E0 * a01[0]))));
                float rad10 = fmaf(q4, a10[4], fmaf(q3, a10[3], fmaf(q2, a10[2], fmaf(q1, a10[1], E0 * a10[0]))));
                float rad11 = fmaf(q4, a11[4], fmaf(q3, a11[3], fmaf(q2, a11[2], fmaf(q1, a11[1], E0 * a11[0]))));
                if (v0) {
                    m0a = fmaf(W000f, n0v0 * rad00, m0a);
                    float dot11 = fmaf(n1x0, ey, fmaf(n1y0, ez, n1z0 * ex));
                    m0b = fmaf(W110f * rad11, dot11, m0b);
                    float t01 = W011f * n0v0 * rad01;
                    m1a0 = fmaf(t01, ey, m1a0);
                    m1a1 = fmaf(t01, ez, m1a1);
                    m1a2 = fmaf(t01, ex, m1a2);
                    float t10 = W101f * rad10;
                    m1b0 = fmaf(t10, n1x0, m1b0);
                    m1b1 = fmaf(t10, n1y0, m1b1);
                    m1b2 = fmaf(t10, n1z0, m1b2);
                    float t11 = W111f * rad11;
                    m1c0 = fmaf(t11, n1y0 * ex - n1z0 * ez, m1c0);
                    m1c1 = fmaf(t11, n1z0 * ey - n1x0 * ex, m1c1);
                    m1c2 = fmaf(t11, n1x0 * ez - n1y0 * ey, m1c2);
                }
            }
            // ---- edge 1 geometry + radials ----
            {
                float ex = rec1.x, ey = rec1.y, ez = rec1.z;
                float r2 = fmaf(ex, ex, fmaf(ey, ey, ez * ez));
                float r  = sqrtf(r2);
                float E0 = __expf(-0.7f * r2);
                float t  = __expf(1.225f * r);
                float q1 = E0 * t, q2 = q1 * t, q3 = q2 * t, q4 = q3 * t;
                float rad00 = fmaf(q4, a00[4], fmaf(q3, a00[3], fmaf(q2, a00[2], fmaf(q1, a00[1], E0 * a00[0]))));
                float rad01 = fmaf(q4, a01[4], fmaf(q3, a01[3], fmaf(q2, a01[2], fmaf(q1, a01[1], E0 * a01[0]))));
                float rad10 = fmaf(q4, a10[4], fmaf(q3, a10[3], fmaf(q2, a10[2], fmaf(q1, a10[1], E0 * a10[0]))));
                float rad11 = fmaf(q4, a11[4], fmaf(q3, a11[3], fmaf(q2, a11[2], fmaf(q1, a11[1], E0 * a11[0]))));
                if (v1) {
                    m0a = fmaf(W000f, n0v1 * rad00, m0a);
                    float dot11 = fmaf(n1x1, ey, fmaf(n1y1, ez, n1z1 * ex));
                    m0b = fmaf(W110f * rad11, dot11, m0b);
                    float t01 = W011f * n0v1 * rad01;
                    m1a0 = fmaf(t01, ey, m1a0);
                    m1a1 = fmaf(t01, ez, m1a1);
                    m1a2 = fmaf(t01, ex, m1a2);
                    float t10 = W101f * rad10;
                    m1b0 = fmaf(t10, n1x1, m1b0);
                    m1b1 = fmaf(t10, n1y1, m1b1);
                    m1b2 = fmaf(t10, n1z1, m1b2);
                    float t11 = W111f * rad11;
                    m1c0 = fmaf(t11, n1y1 * ex - n1z1 * ez, m1c0);
                    m1c1 = fmaf(t11, n1z1 * ey - n1x1 * ex, m1c1);
                    m1c2 = fmaf(t11, n1x1 * ez - n1y1 * ey, m1c2);
                }
            }
        }
    }

    // Combine halves within each warp.
    const unsigned FULL = 0xffffffffu;
    m0a  += __shfl_xor_sync(FULL, m0a, 16);
    m0b  += __shfl_xor_sync(FULL, m0b, 16);
    m1a0 += __shfl_xor_sync(FULL, m1a0, 16);
    m1a1 += __shfl_xor_sync(FULL, m1a1, 16);
    m1a2 += __shfl_xor_sync(FULL, m1a2, 16);
    m1b0 += __shfl_xor_sync(FULL, m1b0, 16);
    m1b1 += __shfl_xor_sync(FULL, m1b1, 16);
    m1b2 += __shfl_xor_sync(FULL, m1b2, 16);
    m1c0 += __shfl_xor_sync(FULL, m1c0, 16);
    m1c1 += __shfl_xor_sync(FULL, m1c1, 16);
    m1c2 += __shfl_xor_sync(FULL, m1c2, 16);

    // Cross-warp (sub) reduction via shared memory.
    if (half == 0) {
        float* r = &red[wid][c * 11];
        r[0] = m0a;  r[1] = m0b;
        r[2] = m1a0; r[3] = m1a1; r[4] = m1a2;
        r[5] = m1b0; r[6] = m1b1; r[7] = m1b2;
        r[8] = m1c0; r[9] = m1c1; r[10] = m1c2;
    }
    __syncthreads();

    if (active && sub == 0 && half == 0) {
        const float* ra = &red[wid][c * 11];
        const float* rb = &red[wid + 1][c * 11];
        float v0 = ra[0] + rb[0];
        float v1 = ra[1] + rb[1];
        out0[node * 32 + c]      = v0;
        out0[node * 32 + 16 + c] = v1;
        float* oa = out1 + ((size_t)node * 48 + c) * 3;
        oa[0] = ra[2] + rb[2]; oa[1] = ra[3] + rb[3]; oa[2] = ra[4] + rb[4];
        float* ob = out1 + ((size_t)node * 48 + 16 + c) * 3;
        ob[0] = ra[5] + rb[5]; ob[1] = ra[6] + rb[6]; ob[2] = ra[7] + rb[7];
        float* oc = out1 + ((size_t)node * 48 + 32 + c) * 3;
        oc[0] = ra[8] + rb[8]; oc[1] = ra[9] + rb[9]; oc[2] = ra[10] + rb[10];
    }
}

extern "C" void kernel_launch(void* const* d_in, const int* in_sizes, int n_in,
                              void* d_out, int out_size) {
    const float* coords  = (const float*)d_in[0];
    const float* nodes0  = (const float*)d_in[1];
    const float* nodes1  = (const float*)d_in[2];
    const float* edges   = (const float*)d_in[3];
    const int*   senders = (const int*)d_in[4];
    const int*   recv    = (const int*)d_in[5];
    const float* c00 = (const float*)d_in[6];
    const float* c01 = (const float*)d_in[7];
    const float* c10 = (const float*)d_in[8];
    const float* c11 = (const float*)d_in[9];
    const float* w000 = (const float*)d_in[10];
    const float* w011 = (const float*)d_in[11];
    const float* w101 = (const float*)d_in[12];
    const float* w110 = (const float*)d_in[13];
    const float* w111 = (const float*)d_in[14];
    float* out = (float*)d_out;

    int N = in_sizes[0] / 3;
    int E = in_sizes[3] / 3;

    cudaMemcpyAsync(out, coords, (size_t)3 * N * sizeof(float),
                    cudaMemcpyDeviceToDevice);
    float* out0 = out + (size_t)3 * N;
    float* out1 = out0 + (size_t)32 * N;

    k_hist<<<(E + 255) / 256, 256>>>(recv, E);
    k_scan<<<1, 1024>>>(N);
    k_scatter<<<(E + 255) / 256, 256>>>(recv, senders, edges, E);
    k_main<<<(N + 3) / 4, 256>>>(nodes0, nodes1,
                                 c00, c01, c10, c11,
                                 w000, w011, w101, w110, w111,
                                 out0, out1, N);
}

// round 9
// speedup vs baseline: 1.7311x; 1.7311x over previous
#include <cuda_runtime.h>
#include <math.h>

#define NCH 16
#define NB 5
#define MAXN 20000
#define MAXE 640000

// Scratch (allocation-free: __device__ globals; zero-initialized at module load)
__device__ int g_counts[MAXN];
__device__ int g_row[MAXN + 1];
__device__ int g_rank[MAXE];
__device__ float4 g_rec[MAXE];    // sorted: {ex, ey, ez, sender_bits}

// Histogram + per-edge rank in one pass. Requires g_counts == 0 on entry
// (true at load; k_scan re-zeroes after reading each call).
__global__ void k_hist(const int* __restrict__ recv, int E) {
    int i = blockIdx.x * blockDim.x + threadIdx.x;
    if (i < E) g_rank[i] = atomicAdd(&g_counts[recv[i]], 1);
}

// Single-block scan: thread-serial ITEMS + shfl warp scan + warp-totals scan.
// Also re-zeroes g_counts for the next kernel_launch call.
__global__ void k_scan(int n) {
    const int T = 1024;
    const int ITEMS = 20;
    int tid = threadIdx.x;
    int lane = tid & 31, wid = tid >> 5;
    int start = tid * ITEMS;

    int loc[ITEMS];
    int sum = 0;
    #pragma unroll
    for (int k = 0; k < ITEMS; k++) {
        int i = start + k;
        int v = (i < n) ? g_counts[i] : 0;
        loc[k] = sum;
        sum += v;
    }
    int s = sum;
    #pragma unroll
    for (int off = 1; off < 32; off <<= 1) {
        int t = __shfl_up_sync(0xffffffffu, s, off);
        if (lane >= off) s += t;
    }
    __shared__ int wsum[32];
    if (lane == 31) wsum[wid] = s;
    __syncthreads();
    if (wid == 0) {
        int w = wsum[lane];
        #pragma unroll
        for (int off = 1; off < 32; off <<= 1) {
            int t = __shfl_up_sync(0xffffffffu, w, off);
            if (lane >= off) w += t;
        }
        wsum[lane] = w;
    }
    __syncthreads();
    int base = (wid > 0 ? wsum[wid - 1] : 0) + (s - sum);
    #pragma unroll
    for (int k = 0; k < ITEMS; k++) {
        int i = start + k;
        if (i < n) { g_row[i] = base + loc[k]; g_counts[i] = 0; }
    }
    if (tid == T - 1) g_row[n] = wsum[31];
}

// Atomic-free scatter: ONE scattered 16-byte store per edge.
__global__ void k_scatter(const int* __restrict__ recv,
                          const int* __restrict__ senders,
                          const float* __restrict__ edges, int E) {
    int i = blockIdx.x * blockDim.x + threadIdx.x;
    if (i >= E) return;
    int pos = g_row[recv[i]] + g_rank[i];
    float ex = edges[3 * i + 0];
    float ey = edges[3 * i + 1];
    float ez = edges[3 * i + 2];
    g_rec[pos] = make_float4(ex, ey, ez, __int_as_float(senders[i]));
}

// Main gather: grid-stride NODE loop per warp. One warp per node at a time;
// preamble (coeffs/weights) paid ONCE per warp, then ~4 nodes each.
// lane = (half<<4)|channel, 4 edges per loop iteration, loads hoisted.
__global__ void __launch_bounds__(256, 4) k_main(
    const float* __restrict__ nodes0, const float* __restrict__ nodes1,
    const float* __restrict__ c00, const float* __restrict__ c01,
    const float* __restrict__ c10, const float* __restrict__ c11,
    const float* __restrict__ w000, const float* __restrict__ w011,
    const float* __restrict__ w101, const float* __restrict__ w110,
    const float* __restrict__ w111,
    float* __restrict__ out0, float* __restrict__ out1, int n_nodes)
{
    int gwarp = (blockIdx.x * blockDim.x + threadIdx.x) >> 5;
    int nwarps = (gridDim.x * blockDim.x) >> 5;
    int lane = threadIdx.x & 31;
    int c = lane & 15;
    int half = lane >> 4;

    // Radial coefficients with RBF constants K_k = exp(-0.7 c_k^2) pre-folded.
    const float Kf[NB] = {
        1.0f,
        (float)exp(-0.7 * 0.875 * 0.875),
        (float)exp(-0.7 * 1.75  * 1.75),
        (float)exp(-0.7 * 2.625 * 2.625),
        (float)exp(-0.7 * 3.5   * 3.5)
    };
    float a00[NB], a01[NB], a10[NB], a11[NB];
    #pragma unroll
    for (int k = 0; k < NB; k++) {
        a00[k] = c00[c * NB + k] * Kf[k];
        a01[k] = c01[c * NB + k] * Kf[k];
        a10[k] = c10[c * NB + k] * Kf[k];
        a11[k] = c11[c * NB + k] * Kf[k];
    }
    const float Y00 = 0.28209479177387814f;
    const float Y1C = 0.4886025119029199f;
    float W000f = w000[c] * Y00;
    float W011f = w011[c] * Y1C;
    float W101f = w101[c] * Y00;
    float W110f = w110[c] * 0.57735026918962576f * Y1C;  // 1/sqrt(3) * Y1C
    float W111f = w111[c] * 0.70710678118654752f * Y1C;  // 1/sqrt(2) * Y1C

    for (int node = gwarp; node < n_nodes; node += nwarps) {
        int rs = g_row[node];
        int re = g_row[node + 1];

        float m0a = 0.f, m0b = 0.f;
        float m1a0 = 0.f, m1a1 = 0.f, m1a2 = 0.f;
        float m1b0 = 0.f, m1b1 = 0.f, m1b2 = 0.f;
        float m1c0 = 0.f, m1c1 = 0.f, m1c2 = 0.f;

        #pragma unroll 1
        for (int base = rs; base < re; base += 4) {
            int i0 = base + half;
            int i1 = base + 2 + half;
            bool v0 = (i0 < re);
            bool v1 = (i1 < re);
            // All memory in flight before compute: 2 recs + node feats for both.
            float4 rec0 = g_rec[v0 ? i0 : rs];
            float4 rec1 = g_rec[v1 ? i1 : rs];
            int s0 = __float_as_int(rec0.w);
            int s1 = __float_as_int(rec1.w);
            float n0v0 = nodes0[s0 * NCH + c];
            float n0v1 = nodes0[s1 * NCH + c];
            const float* p0 = nodes1 + ((size_t)s0 * NCH + c) * 3;
            const float* p1 = nodes1 + ((size_t)s1 * NCH + c) * 3;
            float n1x0 = p0[0], n1y0 = p0[1], n1z0 = p0[2];
            float n1x1 = p1[0], n1y1 = p1[1], n1z1 = p1[2];

            // ---- edge 0 ----
            {
                float ex = rec0.x, ey = rec0.y, ez = rec0.z;
                float r2 = fmaf(ex, ex, fmaf(ey, ey, ez * ez));
                float r  = sqrtf(r2);
                float E0 = __expf(-0.7f * r2);
                float t  = __expf(1.225f * r);
                float q1 = E0 * t, q2 = q1 * t, q3 = q2 * t, q4 = q3 * t;
                float rad00 = fmaf(q4, a00[4], fmaf(q3, a00[3], fmaf(q2, a00[2], fmaf(q1, a00[1], E0 * a00[0]))));
                float rad01 = fmaf(q4, a01[4], fmaf(q3, a01[3], fmaf(q2, a01[2], fmaf(q1, a01[1], E0 * a01[0]))));
                float rad10 = fmaf(q4, a10[4], fmaf(q3, a10[3], fmaf(q2, a10[2], fmaf(q1, a10[1], E0 * a10[0]))));
                float rad11 = fmaf(q4, a11[4], fmaf(q3, a11[3], fmaf(q2, a11[2], fmaf(q1, a11[1], E0 * a11[0]))));
                if (v0) {
                    m0a = fmaf(W000f, n0v0 * rad00, m0a);
                    float dot11 = fmaf(n1x0, ey, fmaf(n1y0, ez, n1z0 * ex));
                    m0b = fmaf(W110f * rad11, dot11, m0b);
                    float t01 = W011f * n0v0 * rad01;
                    m1a0 = fmaf(t01, ey, m1a0);
                    m1a1 = fmaf(t01, ez, m1a1);
                    m1a2 = fmaf(t01, ex, m1a2);
                    float t10 = W101f * rad10;
                    m1b0 = fmaf(t10, n1x0, m1b0);
                    m1b1 = fmaf(t10, n1y0, m1b1);
                    m1b2 = fmaf(t10, n1z0, m1b2);
                    float t11 = W111f * rad11;
                    m1c0 = fmaf(t11, n1y0 * ex - n1z0 * ez, m1c0);
                    m1c1 = fmaf(t11, n1z0 * ey - n1x0 * ex, m1c1);
                    m1c2 = fmaf(t11, n1x0 * ez - n1y0 * ey, m1c2);
                }
            }
            // ---- edge 1 ----
            {
                float ex = rec1.x, ey = rec1.y, ez = rec1.z;
                float r2 = fmaf(ex, ex, fmaf(ey, ey, ez * ez));
                float r  = sqrtf(r2);
                float E0 = __expf(-0.7f * r2);
                float t  = __expf(1.225f * r);
                float q1 = E0 * t, q2 = q1 * t, q3 = q2 * t, q4 = q3 * t;
                float rad00 = fmaf(q4, a00[4], fmaf(q3, a00[3], fmaf(q2, a00[2], fmaf(q1, a00[1], E0 * a00[0]))));
                float rad01 = fmaf(q4, a01[4], fmaf(q3, a01[3], fmaf(q2, a01[2], fmaf(q1, a01[1], E0 * a01[0]))));
                float rad10 = fmaf(q4, a10[4], fmaf(q3, a10[3], fmaf(q2, a10[2], fmaf(q1, a10[1], E0 * a10[0]))));
                float rad11 = fmaf(q4, a11[4], fmaf(q3, a11[3], fmaf(q2, a11[2], fmaf(q1, a11[1], E0 * a11[0]))));
                if (v1) {
                    m0a = fmaf(W000f, n0v1 * rad00, m0a);
                    float dot11 = fmaf(n1x1, ey, fmaf(n1y1, ez, n1z1 * ex));
                    m0b = fmaf(W110f * rad11, dot11, m0b);
                    float t01 = W011f * n0v1 * rad01;
                    m1a0 = fmaf(t01, ey, m1a0);
                    m1a1 = fmaf(t01, ez, m1a1);
                    m1a2 = fmaf(t01, ex, m1a2);
                    float t10 = W101f * rad10;
                    m1b0 = fmaf(t10, n1x1, m1b0);
                    m1b1 = fmaf(t10, n1y1, m1b1);
                    m1b2 = fmaf(t10, n1z1, m1b2);
                    float t11 = W111f * rad11;
                    m1c0 = fmaf(t11, n1y1 * ex - n1z1 * ez, m1c0);
                    m1c1 = fmaf(t11, n1z1 * ey - n1x1 * ex, m1c1);
                    m1c2 = fmaf(t11, n1x1 * ez - n1y1 * ey, m1c2);
                }
            }
        }

        // Combine the two half-warps and store this node's outputs.
        const unsigned FULL = 0xffffffffu;
        m0a  += __shfl_xor_sync(FULL, m0a, 16);
        m0b  += __shfl_xor_sync(FULL, m0b, 16);
        m1a0 += __shfl_xor_sync(FULL, m1a0, 16);
        m1a1 += __shfl_xor_sync(FULL, m1a1, 16);
        m1a2 += __shfl_xor_sync(FULL, m1a2, 16);
        m1b0 += __shfl_xor_sync(FULL, m1b0, 16);
        m1b1 += __shfl_xor_sync(FULL, m1b1, 16);
        m1b2 += __shfl_xor_sync(FULL, m1b2, 16);
        m1c0 += __shfl_xor_sync(FULL, m1c0, 16);
        m1c1 += __shfl_xor_sync(FULL, m1c1, 16);
        m1c2 += __shfl_xor_sync(FULL, m1c2, 16);

        if (half == 0) {
            out0[node * 32 + c]      = m0a;
            out0[node * 32 + 16 + c] = m0b;
            float* oa = out1 + ((size_t)node * 48 + c) * 3;
            oa[0] = m1a0; oa[1] = m1a1; oa[2] = m1a2;
            float* ob = out1 + ((size_t)node * 48 + 16 + c) * 3;
            ob[0] = m1b0; ob[1] = m1b1; ob[2] = m1b2;
            float* oc = out1 + ((size_t)node * 48 + 32 + c) * 3;
            oc[0] = m1c0; oc[1] = m1c1; oc[2] = m1c2;
        }
    }
}

extern "C" void kernel_launch(void* const* d_in, const int* in_sizes, int n_in,
                              void* d_out, int out_size) {
    const float* coords  = (const float*)d_in[0];
    const float* nodes0  = (const float*)d_in[1];
    const float* nodes1  = (const float*)d_in[2];
    const float* edges   = (const float*)d_in[3];
    const int*   senders = (const int*)d_in[4];
    const int*   recv    = (const int*)d_in[5];
    const float* c00 = (const float*)d_in[6];
    const float* c01 = (const float*)d_in[7];
    const float* c10 = (const float*)d_in[8];
    const float* c11 = (const float*)d_in[9];
    const float* w000 = (const float*)d_in[10];
    const float* w011 = (const float*)d_in[11];
    const float* w101 = (const float*)d_in[12];
    const float* w110 = (const float*)d_in[13];
    const float* w111 = (const float*)d_in[14];
    float* out = (float*)d_out;

    int N = in_sizes[0] / 3;
    int E = in_sizes[3] / 3;

    cudaMemcpyAsync(out, coords, (size_t)3 * N * sizeof(float),
                    cudaMemcpyDeviceToDevice);
    float* out0 = out + (size_t)3 * N;
    float* out1 = out0 + (size_t)32 * N;

    k_hist<<<(E + 255) / 256, 256>>>(recv, E);
    k_scan<<<1, 1024>>>(N);
    k_scatter<<<(E + 255) / 256, 256>>>(recv, senders, edges, E);
    // Full-residency persistent-ish grid: 592 blocks x 8 warps = 4736 warps
    // (32 warps/SM x 148 SMs); each warp walks ~4.2 nodes, preamble paid once.
    k_main<<<592, 256>>>(nodes0, nodes1,
                         c00, c01, c10, c11,
                         w000, w011, w101, w110, w111,
                         out0, out1, N);
}

// round 10
// speedup vs baseline: 1.8212x; 1.0520x over previous
#include <cuda_runtime.h>
#include <math.h>

#define NCH 16
#define NB 5
#define MAXN 20000
#define MAXE 640000

// Scratch (allocation-free: __device__ globals; zero-initialized at module load)
__device__ int g_counts[MAXN];
__device__ int g_row[MAXN + 1];
__device__ int g_rank[MAXE];
__device__ float4 g_rec[MAXE];    // sorted: {ex, ey, ez, sender_bits}

// Histogram + per-edge rank in one pass. Requires g_counts == 0 on entry
// (true at load; k_scan re-zeroes after reading each call).
__global__ void k_hist(const int* __restrict__ recv, int E) {
    int i = blockIdx.x * blockDim.x + threadIdx.x;
    if (i < E) g_rank[i] = atomicAdd(&g_counts[recv[i]], 1);
}

// Single-block scan: thread-serial ITEMS + shfl warp scan + warp-totals scan.
// Also re-zeroes g_counts for the next kernel_launch call.
__global__ void k_scan(int n) {
    const int T = 1024;
    const int ITEMS = 20;
    int tid = threadIdx.x;
    int lane = tid & 31, wid = tid >> 5;
    int start = tid * ITEMS;

    int loc[ITEMS];
    int sum = 0;
    #pragma unroll
    for (int k = 0; k < ITEMS; k++) {
        int i = start + k;
        int v = (i < n) ? g_counts[i] : 0;
        loc[k] = sum;
        sum += v;
    }
    int s = sum;
    #pragma unroll
    for (int off = 1; off < 32; off <<= 1) {
        int t = __shfl_up_sync(0xffffffffu, s, off);
        if (lane >= off) s += t;
    }
    __shared__ int wsum[32];
    if (lane == 31) wsum[wid] = s;
    __syncthreads();
    if (wid == 0) {
        int w = wsum[lane];
        #pragma unroll
        for (int off = 1; off < 32; off <<= 1) {
            int t = __shfl_up_sync(0xffffffffu, w, off);
            if (lane >= off) w += t;
        }
        wsum[lane] = w;
    }
    __syncthreads();
    int base = (wid > 0 ? wsum[wid - 1] : 0) + (s - sum);
    #pragma unroll
    for (int k = 0; k < ITEMS; k++) {
        int i = start + k;
        if (i < n) { g_row[i] = base + loc[k]; g_counts[i] = 0; }
    }
    if (tid == T - 1) g_row[n] = wsum[31];
}

// Atomic-free scatter: ONE scattered 16-byte store per edge.
__global__ void k_scatter(const int* __restrict__ recv,
                          const int* __restrict__ senders,
                          const float* __restrict__ edges, int E) {
    int i = blockIdx.x * blockDim.x + threadIdx.x;
    if (i >= E) return;
    int pos = g_row[recv[i]] + g_rank[i];
    float ex = edges[3 * i + 0];
    float ey = edges[3 * i + 1];
    float ez = edges[3 * i + 2];
    g_rec[pos] = make_float4(ex, ey, ez, __int_as_float(senders[i]));
}

// Main gather: grid-stride NODE loop per warp, preamble paid once per warp.
// lane = (half<<4)|channel, 4 edges per iteration.
// Software pipeline: recs for iter i+1 prefetched during iter i, so node
// gathers issue at iteration start and radial FMAs overlap their latency.
__global__ void __launch_bounds__(256, 4) k_main(
    const float* __restrict__ nodes0, const float* __restrict__ nodes1,
    const float* __restrict__ c00, const float* __restrict__ c01,
    const float* __restrict__ c10, const float* __restrict__ c11,
    const float* __restrict__ w000, const float* __restrict__ w011,
    const float* __restrict__ w101, const float* __restrict__ w110,
    const float* __restrict__ w111,
    float* __restrict__ out0, float* __restrict__ out1, int n_nodes)
{
    int gwarp = (blockIdx.x * blockDim.x + threadIdx.x) >> 5;
    int nwarps = (gridDim.x * blockDim.x) >> 5;
    int lane = threadIdx.x & 31;
    int c = lane & 15;
    int half = lane >> 4;

    // Radial coefficients: RBF constants K_k AND path weights pre-folded.
    const float Kf[NB] = {
        1.0f,
        (float)exp(-0.7 * 0.875 * 0.875),
        (float)exp(-0.7 * 1.75  * 1.75),
        (float)exp(-0.7 * 2.625 * 2.625),
        (float)exp(-0.7 * 3.5   * 3.5)
    };
    const float Y00 = 0.28209479177387814f;
    const float Y1C = 0.4886025119029199f;
    float W000f = w000[c] * Y00;
    float W011f = w011[c] * Y1C;
    float W101f = w101[c] * Y00;
    float W110f = w110[c] * 0.57735026918962576f * Y1C;  // 1/sqrt(3) * Y1C
    float W111f = w111[c] * 0.70710678118654752f * Y1C;  // 1/sqrt(2) * Y1C

    float a00[NB], a01[NB], a10[NB], a11[NB];
    #pragma unroll
    for (int k = 0; k < NB; k++) {
        a00[k] = c00[c * NB + k] * Kf[k] * W000f;   // rad00 pre-weighted
        a01[k] = c01[c * NB + k] * Kf[k] * W011f;   // rad01 pre-weighted
        a10[k] = c10[c * NB + k] * Kf[k] * W101f;   // rad10 pre-weighted
        a11[k] = c11[c * NB + k] * Kf[k];           // rad11 raw (two weights)
    }

    for (int node = gwarp; node < n_nodes; node += nwarps) {
        int rs = g_row[node];
        int re = g_row[node + 1];

        float m0a = 0.f, m0b = 0.f;
        float m1a0 = 0.f, m1a1 = 0.f, m1a2 = 0.f;
        float m1b0 = 0.f, m1b1 = 0.f, m1b2 = 0.f;
        float m1c0 = 0.f, m1c1 = 0.f, m1c2 = 0.f;

        // Pipeline prologue: recs for first iteration.
        int i0 = rs + half;
        int i1 = rs + 2 + half;
        bool v0 = (i0 < re);
        bool v1 = (i1 < re);
        float4 rec0 = g_rec[v0 ? i0 : rs];
        float4 rec1 = g_rec[v1 ? i1 : rs];

        #pragma unroll 1
        for (int base = rs; base < re; base += 4) {
            // Node gathers for CURRENT edges — senders already in registers.
            int s0 = __float_as_int(rec0.w);
            int s1 = __float_as_int(rec1.w);
            float n0v0 = nodes0[s0 * NCH + c];
            float n0v1 = nodes0[s1 * NCH + c];
            const float* p0 = nodes1 + ((size_t)s0 * NCH + c) * 3;
            const float* p1 = nodes1 + ((size_t)s1 * NCH + c) * 3;
            float n1x0 = p0[0], n1y0 = p0[1], n1z0 = p0[2];
            float n1x1 = p1[0], n1y1 = p1[1], n1z1 = p1[2];

            // Prefetch NEXT iteration's recs (safe index rs past the end).
            int j0 = base + 4 + half;
            int j1 = base + 6 + half;
            bool w0 = (j0 < re);
            bool w1 = (j1 < re);
            float4 nrec0 = g_rec[w0 ? j0 : rs];
            float4 nrec1 = g_rec[w1 ? j1 : rs];

            // Radials for both edges (geometry only) — overlap node latency.
            float ex0 = rec0.x, ey0 = rec0.y, ez0 = rec0.z;
            float ex1 = rec1.x, ey1 = rec1.y, ez1 = rec1.z;
            float r2a = fmaf(ex0, ex0, fmaf(ey0, ey0, ez0 * ez0));
            float r2b = fmaf(ex1, ex1, fmaf(ey1, ey1, ez1 * ez1));
            float ra  = sqrtf(r2a);
            float rb  = sqrtf(r2b);
            float E0a = __expf(-0.7f * r2a);
            float E0b = __expf(-0.7f * r2b);
            float ta  = __expf(1.225f * ra);
            float tb  = __expf(1.225f * rb);
            float qa1 = E0a * ta, qa2 = qa1 * ta, qa3 = qa2 * ta, qa4 = qa3 * ta;
            float qb1 = E0b * tb, qb2 = qb1 * tb, qb3 = qb2 * tb, qb4 = qb3 * tb;

            float rad00a = fmaf(qa4, a00[4], fmaf(qa3, a00[3], fmaf(qa2, a00[2], fmaf(qa1, a00[1], E0a * a00[0]))));
            float rad01a = fmaf(qa4, a01[4], fmaf(qa3, a01[3], fmaf(qa2, a01[2], fmaf(qa1, a01[1], E0a * a01[0]))));
            float rad10a = fmaf(qa4, a10[4], fmaf(qa3, a10[3], fmaf(qa2, a10[2], fmaf(qa1, a10[1], E0a * a10[0]))));
            float rad11a = fmaf(qa4, a11[4], fmaf(qa3, a11[3], fmaf(qa2, a11[2], fmaf(qa1, a11[1], E0a * a11[0]))));
            float rad00b = fmaf(qb4, a00[4], fmaf(qb3, a00[3], fmaf(qb2, a00[2], fmaf(qb1, a00[1], E0b * a00[0]))));
            float rad01b = fmaf(qb4, a01[4], fmaf(qb3, a01[3], fmaf(qb2, a01[2], fmaf(qb1, a01[1], E0b * a01[0]))));
            float rad10b = fmaf(qb4, a10[4], fmaf(qb3, a10[3], fmaf(qb2, a10[2], fmaf(qb1, a10[1], E0b * a10[0]))));
            float rad11b = fmaf(qb4, a11[4], fmaf(qb3, a11[3], fmaf(qb2, a11[2], fmaf(qb1, a11[1], E0b * a11[0]))));

            // Consume node features (arrived during radial compute).
            if (v0) {
                m0a = fmaf(n0v0, rad00a, m0a);
                float dot11 = fmaf(n1x0, ey0, fmaf(n1y0, ez0, n1z0 * ex0));
                m0b = fmaf(W110f * rad11a, dot11, m0b);
                float t01 = n0v0 * rad01a;
                m1a0 = fmaf(t01, ey0, m1a0);
                m1a1 = fmaf(t01, ez0, m1a1);
                m1a2 = fmaf(t01, ex0, m1a2);
                m1b0 = fmaf(rad10a, n1x0, m1b0);
                m1b1 = fmaf(rad10a, n1y0, m1b1);
                m1b2 = fmaf(rad10a, n1z0, m1b2);
                float t11 = W111f * rad11a;
                m1c0 = fmaf(t11, n1y0 * ex0 - n1z0 * ez0, m1c0);
                m1c1 = fmaf(t11, n1z0 * ey0 - n1x0 * ex0, m1c1);
                m1c2 = fmaf(t11, n1x0 * ez0 - n1y0 * ey0, m1c2);
            }
            if (v1) {
                m0a = fmaf(n0v1, rad00b, m0a);
                float dot11 = fmaf(n1x1, ey1, fmaf(n1y1, ez1, n1z1 * ex1));
                m0b = fmaf(W110f * rad11b, dot11, m0b);
                float t01 = n0v1 * rad01b;
                m1a0 = fmaf(t01, ey1, m1a0);
                m1a1 = fmaf(t01, ez1, m1a1);
                m1a2 = fmaf(t01, ex1, m1a2);
                m1b0 = fmaf(rad10b, n1x1, m1b0);
                m1b1 = fmaf(rad10b, n1y1, m1b1);
                m1b2 = fmaf(rad10b, n1z1, m1b2);
                float t11 = W111f * rad11b;
                m1c0 = fmaf(t11, n1y1 * ex1 - n1z1 * ez1, m1c0);
                m1c1 = fmaf(t11, n1z1 * ey1 - n1x1 * ex1, m1c1);
                m1c2 = fmaf(t11, n1x1 * ez1 - n1y1 * ey1, m1c2);
            }

            // Rotate pipeline.
            rec0 = nrec0; rec1 = nrec1;
            v0 = w0; v1 = w1;
        }

        // Combine the two half-warps and store this node's outputs.
        const unsigned FULL = 0xffffffffu;
        m0a  += __shfl_xor_sync(FULL, m0a, 16);
        m0b  += __shfl_xor_sync(FULL, m0b, 16);
        m1a0 += __shfl_xor_sync(FULL, m1a0, 16);
        m1a1 += __shfl_xor_sync(FULL, m1a1, 16);
        m1a2 += __shfl_xor_sync(FULL, m1a2, 16);
        m1b0 += __shfl_xor_sync(FULL, m1b0, 16);
        m1b1 += __shfl_xor_sync(FULL, m1b1, 16);
        m1b2 += __shfl_xor_sync(FULL, m1b2, 16);
        m1c0 += __shfl_xor_sync(FULL, m1c0, 16);
        m1c1 += __shfl_xor_sync(FULL, m1c1, 16);
        m1c2 += __shfl_xor_sync(FULL, m1c2, 16);

        if (half == 0) {
            out0[node * 32 + c]      = m0a;
            out0[node * 32 + 16 + c] = m0b;
            float* oa = out1 + ((size_t)node * 48 + c) * 3;
            oa[0] = m1a0; oa[1] = m1a1; oa[2] = m1a2;
            float* ob = out1 + ((size_t)node * 48 + 16 + c) * 3;
            ob[0] = m1b0; ob[1] = m1b1; ob[2] = m1b2;
            float* oc = out1 + ((size_t)node * 48 + 32 + c) * 3;
            oc[0] = m1c0; oc[1] = m1c1; oc[2] = m1c2;
        }
    }
}

extern "C" void kernel_launch(void* const* d_in, const int* in_sizes, int n_in,
                              void* d_out, int out_size) {
    const float* coords  = (const float*)d_in[0];
    const float* nodes0  = (const float*)d_in[1];
    const float* nodes1  = (const float*)d_in[2];
    const float* edges   = (const float*)d_in[3];
    const int*   senders = (const int*)d_in[4];
    const int*   recv    = (const int*)d_in[5];
    const float* c00 = (const float*)d_in[6];
    const float* c01 = (const float*)d_in[7];
    const float* c10 = (const float*)d_in[8];
    const float* c11 = (const float*)d_in[9];
    const float* w000 = (const float*)d_in[10];
    const float* w011 = (const float*)d_in[11];
    const float* w101 = (const float*)d_in[12];
    const float* w110 = (const float*)d_in[13];
    const float* w111 = (const float*)d_in[14];
    float* out = (float*)d_out;

    int N = in_sizes[0] / 3;
    int E = in_sizes[3] / 3;

    cudaMemcpyAsync(out, coords, (size_t)3 * N * sizeof(float),
                    cudaMemcpyDeviceToDevice);
    float* out0 = out + (size_t)3 * N;
    float* out1 = out0 + (size_t)32 * N;

    k_hist<<<(E + 255) / 256, 256>>>(recv, E);
    k_scan<<<1, 1024>>>(N);
    k_scatter<<<(E + 255) / 256, 256>>>(recv, senders, edges, E);
    // Full-residency grid: 592 blocks x 8 warps = 4736 warps
    // (32 warps/SM x 148 SMs); each warp walks ~4.2 nodes.
    k_main<<<592, 256>>>(nodes0, nodes1,
                         c00, c01, c10, c11,
                         w000, w011, w101, w110, w111,
                         out0, out1, N);
}